// round 7
// baseline (speedup 1.0000x reference)
#include <cuda_runtime.h>
#include <cuda_bf16.h>
#include <cstdint>

#define SLEN 2048
#define NI   768
#define NH   12
#define DH   64
#define NB   2
#define MTOT (NB * SLEN)       // 4096
#define NBH (NB * NH)          // 24

typedef __nv_bfloat16  bf16;
typedef __nv_bfloat162 bf162;

// scale folded into Q: (1/8) * log2(e)
#define QSCALE 0.1803368801111725f

// ---------------------------------------------------------------------------
// Device-global scratch (allocation-free).  Activations/weights stored as two
// sections (hi, lo); the GEMM loader remaps logical K-chunks onto sections:
//   A sections {hi, lo, hi} x B sections {hi, hi, lo}  -> 3-term split product
// ---------------------------------------------------------------------------
__device__ __align__(256) bf16 g_Ah[(size_t)MTOT * NI];
__device__ __align__(256) bf16 g_Al[(size_t)MTOT * NI];
__device__ __align__(256) bf16 g_Wqh[(size_t)(3 * NI) * NI];  // [n][k] n=2304
__device__ __align__(256) bf16 g_Wql[(size_t)(3 * NI) * NI];
__device__ __align__(256) bf16 g_Wph[(size_t)NI * NI];
__device__ __align__(256) bf16 g_Wpl[(size_t)NI * NI];
__device__ __align__(256) bf16 g_Qh[NBH * SLEN * DH];   // pre-scaled by QSCALE
__device__ __align__(256) bf16 g_Ql[NBH * SLEN * DH];
__device__ __align__(256) bf16 g_Kh[NBH * SLEN * DH];
__device__ __align__(256) bf16 g_Kl[NBH * SLEN * DH];
__device__ __align__(256) bf16 g_Vh[NBH * SLEN * DH];
__device__ __align__(256) bf16 g_Vl[NBH * SLEN * DH];

// ---------------------------------------------------------------------------
// PTX helpers (sm_80+ only)
// ---------------------------------------------------------------------------
__device__ __forceinline__ uint32_t smem_u32(const void* p) {
    uint32_t a;
    asm("{ .reg .u64 t; cvta.to.shared.u64 t, %1; cvt.u32.u64 %0, t; }" : "=r"(a) : "l"(p));
    return a;
}

#define LDSM_X4(r0, r1, r2, r3, addr) \
    asm volatile("ldmatrix.sync.aligned.m8n8.x4.shared.b16 {%0,%1,%2,%3}, [%4];" \
        : "=r"(r0), "=r"(r1), "=r"(r2), "=r"(r3) : "r"(addr))
#define LDSM_X4_T(r0, r1, r2, r3, addr) \
    asm volatile("ldmatrix.sync.aligned.m8n8.x4.trans.shared.b16 {%0,%1,%2,%3}, [%4];" \
        : "=r"(r0), "=r"(r1), "=r"(r2), "=r"(r3) : "r"(addr))

__device__ __forceinline__ void mma_bf16(float* d, const uint32_t* a, const uint32_t* b) {
    asm volatile(
        "mma.sync.aligned.m16n8k16.row.col.f32.bf16.bf16.f32 "
        "{%0,%1,%2,%3}, {%4,%5,%6,%7}, {%8,%9}, {%0,%1,%2,%3};"
        : "+f"(d[0]), "+f"(d[1]), "+f"(d[2]), "+f"(d[3])
        : "r"(a[0]), "r"(a[1]), "r"(a[2]), "r"(a[3]), "r"(b[0]), "r"(b[1]));
}

#define CP_ASYNC16(sa, gp) \
    asm volatile("cp.async.cg.shared.global [%0], [%1], 16;" :: "r"(sa), "l"(gp))
#define CP_COMMIT() asm volatile("cp.async.commit_group;")
#define CP_WAIT(n)  asm volatile("cp.async.wait_group %0;" :: "n"(n))

__device__ __forceinline__ uint32_t swz(uint32_t base, int row, int chunk) {
    return base + row * 128 + (((chunk ^ (row & 7))) << 4);
}

__device__ __forceinline__ uint32_t packbf(float x, float y) {
    bf162 t = __floats2bfloat162_rn(x, y);
    return *reinterpret_cast<uint32_t*>(&t);
}

__device__ __forceinline__ float ex2(float x) {
    float y;
    asm("ex2.approx.f32 %0, %1;" : "=f"(y) : "f"(x));
    return y;
}

// ---------------------------------------------------------------------------
// Split preps
// ---------------------------------------------------------------------------
__global__ void split_act_kernel(const float* __restrict__ src) {
    int idx = blockIdx.x * blockDim.x + threadIdx.x;
    if (idx >= MTOT * NI) return;
    float x = src[idx];
    bf16 hi = __float2bfloat16(x);
    bf16 lo = __float2bfloat16(x - __bfloat162float(hi));
    g_Ah[idx] = hi;
    g_Al[idx] = lo;
}

// W [768, Ncols] -> hi/lo [Ncols][768] (transposed)
__global__ void split_w_kernel(const float* __restrict__ W,
                               bf16* __restrict__ dh, bf16* __restrict__ dl,
                               int Ncols) {
    __shared__ float t[32][33];
    int n0 = blockIdx.x * 32, k0 = blockIdx.y * 32;
    #pragma unroll
    for (int i = 0; i < 4; i++) {
        int k = k0 + threadIdx.y + i * 8;
        t[threadIdx.y + i * 8][threadIdx.x] = W[(size_t)k * Ncols + n0 + threadIdx.x];
    }
    __syncthreads();
    #pragma unroll
    for (int i = 0; i < 4; i++) {
        int n = n0 + threadIdx.y + i * 8;
        int k = k0 + threadIdx.x;
        float x = t[threadIdx.x][threadIdx.y + i * 8];
        bf16 hi = __float2bfloat16(x);
        bf16 lo = __float2bfloat16(x - __bfloat162float(hi));
        dh[(size_t)n * NI + k] = hi;
        dl[(size_t)n * NI + k] = lo;
    }
}

// ---------------------------------------------------------------------------
// mma.sync GEMM: C[M,N] = sum over 36 logical chunks of A_sec @ B_sec^T (+bias)
// CTA 128x128, BK=64, 3-stage cp.async, single sync per chunk.
// MODE 0: scatter into Q/K/V hi+lo (Q pre-scaled).  MODE 1: fp32 C.
// ---------------------------------------------------------------------------
#define BM 128
#define BN 128
#define BK 64
#define NCH 36                    // 3 sections x 12 chunks
#define GSTAGE 32768
#define GEMM_SMEM (3 * GSTAGE)

template <int MODE>
__global__ __launch_bounds__(256, 2)
void gemm_tc(const bf16* __restrict__ Ah, const bf16* __restrict__ Al,
             const bf16* __restrict__ Bh, const bf16* __restrict__ Bl,
             const float* __restrict__ bias, float* __restrict__ Cout, int Ntot)
{
    extern __shared__ char smem[];
    const uint32_t sb = smem_u32(smem);
    const int tid = threadIdx.x;
    const int warp = tid >> 5;
    const int lane = tid & 31;
    const int wm = (warp >> 1) * 32;
    const int wn = (warp & 1) * 64;
    const int bm = blockIdx.y * BM;
    const int bn = blockIdx.x * BN;

    float acc[2][8][4] = {};

    auto issue = [&](int c, int st) {
        int sec = c / 12;
        int cc  = c - sec * 12;
        const char* As = (const char*)((sec == 1) ? Al : Ah);
        const char* Bs = (const char*)((sec == 2) ? Bl : Bh);
        uint32_t abase = sb + st * GSTAGE;
        uint32_t bbase = abase + 16384;
        #pragma unroll
        for (int i = 0; i < 4; i++) {
            int id = tid + i * 256;
            int r = id >> 3, ch = id & 7;
            CP_ASYNC16(swz(abase, r, ch),
                       As + ((size_t)(bm + r) * NI + cc * BK) * 2 + ch * 16);
        }
        #pragma unroll
        for (int i = 0; i < 4; i++) {
            int id = tid + i * 256;
            int r = id >> 3, ch = id & 7;
            CP_ASYNC16(swz(bbase, r, ch),
                       Bs + ((size_t)(bn + r) * NI + cc * BK) * 2 + ch * 16);
        }
        CP_COMMIT();
    };

    issue(0, 0);
    issue(1, 1);

    for (int c = 0; c < NCH; c++) {
        const int st = c - (c / 3) * 3;
        if (c == NCH - 1) { CP_WAIT(0); } else { CP_WAIT(1); }
        __syncthreads();          // chunk c visible; all warps done with c-1
        if (c + 2 < NCH) issue(c + 2, (c + 2) - ((c + 2) / 3) * 3);

        uint32_t abase = sb + st * GSTAGE;
        uint32_t bbase = abase + 16384;
        const int t = lane >> 3;

        #pragma unroll
        for (int ks = 0; ks < 4; ks++) {
            uint32_t a[2][4];
            #pragma unroll
            for (int mt = 0; mt < 2; mt++) {
                int row = wm + mt * 16 + (t & 1) * 8 + (lane & 7);
                LDSM_X4(a[mt][0], a[mt][1], a[mt][2], a[mt][3],
                        swz(abase, row, 2 * ks + (t >> 1)));
            }
            #pragma unroll
            for (int ntp = 0; ntp < 4; ntp++) {
                uint32_t b4[4];
                int row = wn + (2 * ntp + ((lane >> 4) & 1)) * 8 + (lane & 7);
                LDSM_X4(b4[0], b4[1], b4[2], b4[3],
                        swz(bbase, row, 2 * ks + ((lane >> 3) & 1)));
                mma_bf16(acc[0][2 * ntp + 0], a[0], b4 + 0);
                mma_bf16(acc[1][2 * ntp + 0], a[1], b4 + 0);
                mma_bf16(acc[0][2 * ntp + 1], a[0], b4 + 2);
                mma_bf16(acc[1][2 * ntp + 1], a[1], b4 + 2);
            }
        }
        // no trailing sync: next iteration's sync provides the guard
    }

    // Epilogue
    #pragma unroll
    for (int mt = 0; mt < 2; mt++) {
        int gr0 = bm + wm + mt * 16 + (lane >> 2);
        #pragma unroll
        for (int nt = 0; nt < 8; nt++) {
            int c0 = bn + wn + nt * 8 + 2 * (lane & 3);
            float b0 = bias[c0], b1 = bias[c0 + 1];
            #pragma unroll
            for (int rr = 0; rr < 2; rr++) {
                int row = gr0 + rr * 8;
                float v0 = acc[mt][nt][rr * 2 + 0] + b0;
                float v1 = acc[mt][nt][rr * 2 + 1] + b1;
                if (MODE == 0) {
                    int h = c0 / 192;
                    int r = c0 - h * 192;
                    int w = r >> 6, dd = r & 63;
                    int b = row >> 11, sI = row & (SLEN - 1);
                    size_t off = ((size_t)((b * NH + h) * SLEN + sI)) * DH + dd;
                    if (w == 0) { v0 *= QSCALE; v1 *= QSCALE; }
                    bf16 h0 = __float2bfloat16(v0);
                    bf16 h1 = __float2bfloat16(v1);
                    bf16 l0 = __float2bfloat16(v0 - __bfloat162float(h0));
                    bf16 l1 = __float2bfloat16(v1 - __bfloat162float(h1));
                    bf16 *dh, *dl;
                    if (w == 0)      { dh = g_Qh; dl = g_Ql; }
                    else if (w == 1) { dh = g_Kh; dl = g_Kl; }
                    else             { dh = g_Vh; dl = g_Vl; }
                    *(bf162*)&dh[off] = bf162(h0, h1);
                    *(bf162*)&dl[off] = bf162(l0, l1);
                } else {
                    float2 v = make_float2(v0, v1);
                    *(float2*)&Cout[(size_t)row * Ntot + c0] = v;
                }
            }
        }
    }
}

// ---------------------------------------------------------------------------
// Flash attention on mma.sync (split-bf16, 3-term), max-free softmax (scale
// pre-folded into Q, base-2 exp).  CTA: 8 warps, Br=128, Bc=64. grid (16, 24).
// smem: Qh,Ql (16K each) + 2 stages x {Kh,Kl,Vh,Vl} (8K each)
// ---------------------------------------------------------------------------
#define ASTAGE 32768
#define ATTN_SMEM (32768 + 2 * ASTAGE)   // 98304
#define NKT (SLEN / 64)                  // 32

__global__ __launch_bounds__(256, 2)
void attn_kernel()
{
    extern __shared__ char smem[];
    const uint32_t sb = smem_u32(smem);
    const uint32_t qh_base = sb;
    const uint32_t ql_base = sb + 16384;
    const uint32_t stg_base = sb + 32768;

    const int tid  = threadIdx.x;
    const int warp = tid >> 5;
    const int lane = tid & 31;
    const int bh   = blockIdx.y;
    const int q0   = blockIdx.x * 128;

    const char* Qhg = (const char*)(g_Qh + ((size_t)bh * SLEN + q0) * DH);
    const char* Qlg = (const char*)(g_Ql + ((size_t)bh * SLEN + q0) * DH);
    const char* Khg = (const char*)(g_Kh + (size_t)bh * SLEN * DH);
    const char* Klg = (const char*)(g_Kl + (size_t)bh * SLEN * DH);
    const char* Vhg = (const char*)(g_Vh + (size_t)bh * SLEN * DH);
    const char* Vlg = (const char*)(g_Vl + (size_t)bh * SLEN * DH);

    // Q tiles: 2 x 128 rows x 128B  (own cp.async group)
    #pragma unroll
    for (int i = 0; i < 8; i++) {
        int id = tid + i * 256;
        int tile = id >> 10;
        int r = (id >> 3) & 127, ch = id & 7;
        const char* src = (tile == 0 ? Qhg : Qlg) + (size_t)r * 128 + ch * 16;
        CP_ASYNC16(swz(tile == 0 ? qh_base : ql_base, r, ch), src);
    }
    CP_COMMIT();

    auto issue_kv = [&](int kt, int st) {
        uint32_t base = stg_base + st * ASTAGE;
        size_t goff = (size_t)kt * 64 * 128;
        #pragma unroll
        for (int i = 0; i < 8; i++) {
            int id = tid + i * 256;
            int tile = id >> 9;
            int r = (id >> 3) & 63, ch = id & 7;
            const char* src;
            if      (tile == 0) src = Khg;
            else if (tile == 1) src = Klg;
            else if (tile == 2) src = Vhg;
            else                src = Vlg;
            src += goff + (size_t)r * 128 + ch * 16;
            CP_ASYNC16(swz(base + tile * 8192, r, ch), src);
        }
        CP_COMMIT();
    };

    issue_kv(0, 0);
    issue_kv(1, 1);

    CP_WAIT(2);                 // Q group done (kv0/kv1 may be in flight)
    __syncthreads();

    // Q fragments -> regs
    uint32_t qh[4][4], ql[4][4];
    {
        const int t = lane >> 3;
        int row = warp * 16 + (t & 1) * 8 + (lane & 7);
        #pragma unroll
        for (int ks = 0; ks < 4; ks++) {
            LDSM_X4(qh[ks][0], qh[ks][1], qh[ks][2], qh[ks][3],
                    swz(qh_base, row, 2 * ks + (t >> 1)));
            LDSM_X4(ql[ks][0], ql[ks][1], ql[ks][2], ql[ks][3],
                    swz(ql_base, row, 2 * ks + (t >> 1)));
        }
    }

    float l0 = 0.f, l1 = 0.f;
    float o[8][4] = {};

    for (int kt = 0; kt < NKT; kt++) {
        const int st = kt & 1;
        if (kt == NKT - 1) { CP_WAIT(0); } else { CP_WAIT(1); }
        __syncthreads();

        uint32_t khb = stg_base + st * ASTAGE;
        uint32_t klb = khb + 8192;
        uint32_t vhb = khb + 16384;
        uint32_t vlb = khb + 24576;

        // ---- S = (Q*c) K^T (3-term split) ----
        float s[8][4] = {};
        #pragma unroll
        for (int ks = 0; ks < 4; ks++) {
            #pragma unroll
            for (int ntp = 0; ntp < 4; ntp++) {
                int row = (2 * ntp + ((lane >> 4) & 1)) * 8 + (lane & 7);
                int ch = 2 * ks + ((lane >> 3) & 1);
                uint32_t bh4[4], bl4[4];
                LDSM_X4(bh4[0], bh4[1], bh4[2], bh4[3], swz(khb, row, ch));
                LDSM_X4(bl4[0], bl4[1], bl4[2], bl4[3], swz(klb, row, ch));
                mma_bf16(s[2 * ntp + 0], qh[ks], bh4 + 0);
                mma_bf16(s[2 * ntp + 0], ql[ks], bh4 + 0);
                mma_bf16(s[2 * ntp + 0], qh[ks], bl4 + 0);
                mma_bf16(s[2 * ntp + 1], qh[ks], bh4 + 2);
                mma_bf16(s[2 * ntp + 1], ql[ks], bh4 + 2);
                mma_bf16(s[2 * ntp + 1], qh[ks], bl4 + 2);
            }
        }

        // ---- max-free softmax: p = 2^s, accumulate row sums ----
        #pragma unroll
        for (int nt = 0; nt < 8; nt++) {
            s[nt][0] = ex2(s[nt][0]);
            s[nt][1] = ex2(s[nt][1]);
            s[nt][2] = ex2(s[nt][2]);
            s[nt][3] = ex2(s[nt][3]);
            l0 += s[nt][0] + s[nt][1];
            l1 += s[nt][2] + s[nt][3];
        }

        // ---- O += P V (3-term split) ----
        #pragma unroll
        for (int j = 0; j < 4; j++) {
            uint32_t ph[4], pl[4];
            #pragma unroll
            for (int half = 0; half < 2; half++) {
                float x0 = s[2 * j + half][0], y0 = s[2 * j + half][1];
                float x1 = s[2 * j + half][2], y1 = s[2 * j + half][3];
                bf16 hx0 = __float2bfloat16(x0), hy0 = __float2bfloat16(y0);
                bf16 hx1 = __float2bfloat16(x1), hy1 = __float2bfloat16(y1);
                ph[half * 2 + 0] = packbf(x0, y0);
                ph[half * 2 + 1] = packbf(x1, y1);
                pl[half * 2 + 0] = packbf(x0 - __bfloat162float(hx0),
                                          y0 - __bfloat162float(hy0));
                pl[half * 2 + 1] = packbf(x1 - __bfloat162float(hx1),
                                          y1 - __bfloat162float(hy1));
            }
            int row = j * 16 + ((lane >> 3) & 1) * 8 + (lane & 7);
            #pragma unroll
            for (int ntp = 0; ntp < 4; ntp++) {
                int ch = 2 * ntp + ((lane >> 4) & 1);
                uint32_t vh4[4], vl4[4];
                LDSM_X4_T(vh4[0], vh4[1], vh4[2], vh4[3], swz(vhb, row, ch));
                LDSM_X4_T(vl4[0], vl4[1], vl4[2], vl4[3], swz(vlb, row, ch));
                mma_bf16(o[2 * ntp + 0], ph, vh4 + 0);
                mma_bf16(o[2 * ntp + 0], pl, vh4 + 0);
                mma_bf16(o[2 * ntp + 0], ph, vl4 + 0);
                mma_bf16(o[2 * ntp + 1], ph, vh4 + 2);
                mma_bf16(o[2 * ntp + 1], pl, vh4 + 2);
                mma_bf16(o[2 * ntp + 1], ph, vl4 + 2);
            }
        }

        __syncthreads();          // all warps done with stage st
        if (kt + 2 < NKT) issue_kv(kt + 2, st);
    }

    // final row sums: reduce across the 4 lanes of the quad
    l0 += __shfl_xor_sync(0xffffffffu, l0, 1);
    l0 += __shfl_xor_sync(0xffffffffu, l0, 2);
    l1 += __shfl_xor_sync(0xffffffffu, l1, 1);
    l1 += __shfl_xor_sync(0xffffffffu, l1, 2);
    float inv0 = 1.0f / l0, inv1 = 1.0f / l1;

    // ---- epilogue -> g_Ah/g_Al (merged heads, split for proj GEMM) ----
    const int b = bh / NH, h = bh - (bh / NH) * NH;
    const int qr = q0 + warp * 16 + (lane >> 2);
    #pragma unroll
    for (int rr = 0; rr < 2; rr++) {
        size_t m = (size_t)b * SLEN + qr + rr * 8;
        float inv = rr ? inv1 : inv0;
        #pragma unroll
        for (int nt = 0; nt < 8; nt++) {
            int c = h * DH + nt * 8 + 2 * (lane & 3);
            float v0 = o[nt][rr * 2 + 0] * inv;
            float v1 = o[nt][rr * 2 + 1] * inv;
            bf16 h0 = __float2bfloat16(v0);
            bf16 h1 = __float2bfloat16(v1);
            bf16 e0 = __float2bfloat16(v0 - __bfloat162float(h0));
            bf16 e1 = __float2bfloat16(v1 - __bfloat162float(h1));
            size_t base = m * NI + c;
            *(bf162*)&g_Ah[base] = bf162(h0, h1);
            *(bf162*)&g_Al[base] = bf162(e0, e1);
        }
    }
}

// ---------------------------------------------------------------------------
extern "C" void kernel_launch(void* const* d_in, const int* in_sizes, int n_in,
                              void* d_out, int out_size)
{
    const float* inp   = (const float*)d_in[0];
    const float* Wqkv  = (const float*)d_in[1];
    const float* bqkv  = (const float*)d_in[2];
    const float* Wproj = (const float*)d_in[3];
    const float* bproj = (const float*)d_in[4];
    float* out = (float*)d_out;

    bf16 *ah, *al, *wqh, *wql, *wph, *wpl;
    cudaGetSymbolAddress((void**)&ah,  g_Ah);
    cudaGetSymbolAddress((void**)&al,  g_Al);
    cudaGetSymbolAddress((void**)&wqh, g_Wqh);
    cudaGetSymbolAddress((void**)&wql, g_Wql);
    cudaGetSymbolAddress((void**)&wph, g_Wph);
    cudaGetSymbolAddress((void**)&wpl, g_Wpl);

    cudaFuncSetAttribute(gemm_tc<0>,
                         cudaFuncAttributeMaxDynamicSharedMemorySize, GEMM_SMEM);
    cudaFuncSetAttribute(gemm_tc<1>,
                         cudaFuncAttributeMaxDynamicSharedMemorySize, GEMM_SMEM);
    cudaFuncSetAttribute(attn_kernel,
                         cudaFuncAttributeMaxDynamicSharedMemorySize, ATTN_SMEM);

    // 1) splits
    {
        int n = MTOT * NI;
        split_act_kernel<<<(n + 255) / 256, 256>>>(inp);
        dim3 blk(32, 8);
        split_w_kernel<<<dim3(3 * NI / 32, NI / 32), blk>>>(Wqkv, wqh, wql, 3 * NI);
        split_w_kernel<<<dim3(NI / 32, NI / 32), blk>>>(Wproj, wph, wpl, NI);
    }
    // 2) QKV GEMM + split scatter into Q/K/V hi/lo (Q pre-scaled)
    {
        dim3 grid(3 * NI / BN, MTOT / BM);   // (18, 32)
        gemm_tc<0><<<grid, 256, GEMM_SMEM>>>(ah, al, wqh, wql, bqkv, nullptr, 3 * NI);
    }
    // 3) Flash attention (mma.sync), writes split O for proj
    {
        dim3 grid(SLEN / 128, NBH);          // (16, 24)
        attn_kernel<<<grid, 256, ATTN_SMEM>>>();
    }
    // 4) proj GEMM -> out
    {
        dim3 grid(NI / BN, MTOT / BM);       // (6, 32)
        gemm_tc<1><<<grid, 256, GEMM_SMEM>>>(ah, al, wph, wpl, bproj, out, NI);
    }
}